// round 15
// baseline (speedup 1.0000x reference)
#include <cuda_runtime.h>

#define B  4
#define Qn 256
#define Kn 1024
#define Dd 512
#define Hh 128
#define DV 512

#define ROWS_ALL (B * Qn + B * Kn)          // 5120 projected rows total

__device__ float g_qh[B * Qn * Hh];         // 512 KB
__device__ float g_kh[B * Kn * Hh];         // 2 MB
__device__ float g_s[B * Qn * Kn];          // 4 MB raw scores
__device__ float g_p[B * Qn * Kn];          // 4 MB normalized probs
__device__ float g_pp[2][ROWS_ALL * Hh];    // 5 MB proj K-split partials
__device__ float g_po[4][B * Qn * DV];      // 8 MB pv K-split partials
__device__ int   g_cnt_p[320];              // proj group counters (zero-init)
__device__ int   g_cnt_s[B * 16];           // score group counters (zero-init)
__device__ int   g_cnt_v[B * 16 * 2];       // pv group counters (zero-init)

__device__ __forceinline__ float ex2a(float x) {
    float r; asm("ex2.approx.f32 %0, %1;" : "=f"(r) : "f"(x)); return r;
}
__device__ __forceinline__ float tanha(float x) {
    float r; asm("tanh.approx.f32 %0, %1;" : "=f"(r) : "f"(x)); return r;
}
__device__ __forceinline__ void fma2(unsigned long long& d, unsigned long long a,
                                     unsigned long long b) {
    asm("fma.rn.f32x2 %0, %1, %2, %0;" : "+l"(d) : "l"(a), "l"(b));
}
__device__ __forceinline__ float2 up2(unsigned long long v) {
    float2 f; asm("mov.b64 {%0, %1}, %2;" : "=f"(f.x), "=f"(f.y) : "l"(v)); return f;
}

// ---------------------------------------------------------------------------
// Projection GEMM with fused last-CTA reduction (R14). Grid 640 x 128.
// ---------------------------------------------------------------------------
__global__ void proj_kernel(const float* __restrict__ Xq, const float* __restrict__ Wq,
                            const float* __restrict__ Xk, const float* __restrict__ Wk) {
    __shared__ float Xs[32 * 36];
    __shared__ float Ws[32 * 68];
    __shared__ int last_s;

    const int bid = blockIdx.x;
    const int rt  = bid >> 2;
    const int ht  = (bid >> 1) & 1;
    const int ks  = bid & 1;
    const int r0  = rt * 32;
    const int h0  = ht * 64;
    const int d0  = ks * 256;
    const int grp = bid >> 1;                // 0..319

    const float* Xbase = (r0 < B * Qn) ? (Xq + (size_t)r0 * Dd)
                                       : (Xk + (size_t)(r0 - B * Qn) * Dd);
    const float* W = (r0 < B * Qn) ? Wq : Wk;

    const int tid = threadIdx.x;
    const int tx  = tid & 15;
    const int ty  = tid >> 4;

    float acc[4][4];
#pragma unroll
    for (int r = 0; r < 4; r++)
#pragma unroll
        for (int c = 0; c < 4; c++) acc[r][c] = 0.0f;

    for (int s = 0; s < 8; s++) {
        const int ds = d0 + s * 32;
        __syncthreads();
#pragma unroll
        for (int i = 0; i < 2; i++) {
            int e = tid + 128 * i;
            int r = e >> 3, c4 = (e & 7) * 4;
            float4 xv = *(const float4*)&Xbase[(size_t)r * Dd + ds + c4];
            Xs[(c4 + 0) * 36 + r] = xv.x;
            Xs[(c4 + 1) * 36 + r] = xv.y;
            Xs[(c4 + 2) * 36 + r] = xv.z;
            Xs[(c4 + 3) * 36 + r] = xv.w;
        }
#pragma unroll
        for (int i = 0; i < 4; i++) {
            int e = tid + 128 * i;
            int h = e >> 3, c4 = (e & 7) * 4;
            float4 wv = *(const float4*)&W[(size_t)(h0 + h) * Dd + ds + c4];
            Ws[(c4 + 0) * 68 + h] = wv.x;
            Ws[(c4 + 1) * 68 + h] = wv.y;
            Ws[(c4 + 2) * 68 + h] = wv.z;
            Ws[(c4 + 3) * 68 + h] = wv.w;
        }
        __syncthreads();
#pragma unroll
        for (int dd = 0; dd < 32; dd++) {
            float4 xv = *(const float4*)&Xs[dd * 36 + ty * 4];
            float4 wv = *(const float4*)&Ws[dd * 68 + tx * 4];
            acc[0][0] += xv.x * wv.x; acc[0][1] += xv.x * wv.y;
            acc[0][2] += xv.x * wv.z; acc[0][3] += xv.x * wv.w;
            acc[1][0] += xv.y * wv.x; acc[1][1] += xv.y * wv.y;
            acc[1][2] += xv.y * wv.z; acc[1][3] += xv.y * wv.w;
            acc[2][0] += xv.z * wv.x; acc[2][1] += xv.z * wv.y;
            acc[2][2] += xv.z * wv.z; acc[2][3] += xv.z * wv.w;
            acc[3][0] += xv.w * wv.x; acc[3][1] += xv.w * wv.y;
            acc[3][2] += xv.w * wv.z; acc[3][3] += xv.w * wv.w;
        }
    }

    float* pp = g_pp[ks];
#pragma unroll
    for (int r = 0; r < 4; r++) {
        float4 o = make_float4(acc[r][0], acc[r][1], acc[r][2], acc[r][3]);
        *(float4*)&pp[(size_t)(r0 + ty * 4 + r) * Hh + h0 + tx * 4] = o;
    }

    __threadfence();
    __syncthreads();
    if (tid == 0) last_s = (atomicAdd(&g_cnt_p[grp], 1) == 1) ? 1 : 0;
    __syncthreads();
    if (last_s) {
        if (tid == 0) g_cnt_p[grp] = 0;      // replay-safe reset
        const float* po = g_pp[1 - ks];
        float* Out = (r0 < B * Qn) ? (g_qh + (size_t)r0 * Hh)
                                   : (g_kh + (size_t)(r0 - B * Qn) * Hh);
#pragma unroll
        for (int r = 0; r < 4; r++) {
            const int rr = ty * 4 + r;
            float4 ov = *(const float4*)&po[(size_t)(r0 + rr) * Hh + h0 + tx * 4];
            float4 o = make_float4(acc[r][0] + ov.x, acc[r][1] + ov.y,
                                   acc[r][2] + ov.z, acc[r][3] + ov.w);
            *(float4*)&Out[(size_t)rr * Hh + h0 + tx * 4] = o;
        }
    }
}

// ---------------------------------------------------------------------------
// Scores kernel with fused last-CTA softmax (R14). Grid = 1024 x 256.
// ---------------------------------------------------------------------------
__global__ void score_kernel(const int* __restrict__ vlens,
                             const float* __restrict__ w_v) {
    __shared__ float kh_s[Hh * 65];
    __shared__ float qh_s[16 * Hh];
    __shared__ float wv_s[Hh];
    __shared__ int last_s;

    const int bx = blockIdx.x;
    const int b  = bx >> 8;
    const int qt = (bx >> 4) & 15;
    const int kt = bx & 15;
    const int q0 = qt * 16;
    const int k0 = kt * 64;
    const int grp = bx >> 4;                 // 0..63

    const int tid  = threadIdx.x;
    const int lane = tid & 31;
    const int w    = tid >> 5;
    const int vl   = vlens[b];

    if (k0 < vl) {
        {
            const float4* src = (const float4*)(g_qh + (size_t)(b * Qn + q0) * Hh);
            ((float4*)qh_s)[tid]       = src[tid];
            ((float4*)qh_s)[tid + 256] = src[tid + 256];
        }
        if (tid < Hh) wv_s[tid] = w_v[tid];

        {
            const float* khg = g_kh + (size_t)(b * Kn + k0) * Hh;
#pragma unroll
            for (int i = 0; i < 8; i++) {
                int e  = tid + 256 * i;
                int kr = e >> 5;
                int h4 = (e & 31) * 4;
                float4 vv = *(const float4*)&khg[(size_t)kr * Hh + h4];
                kh_s[(h4 + 0) * 65 + kr] = vv.x;
                kh_s[(h4 + 1) * 65 + kr] = vv.y;
                kh_s[(h4 + 2) * 65 + kr] = vv.z;
                kh_s[(h4 + 3) * 65 + kr] = vv.w;
            }
        }
        __syncthreads();

        const float* q0p = qh_s + (2 * w) * Hh;
        const float* q1p = qh_s + (2 * w + 1) * Hh;

        float s00 = 0.f, s01 = 0.f, s10 = 0.f, s11 = 0.f;
#pragma unroll 4
        for (int h = 0; h < Hh; h++) {
            float ka = kh_s[h * 65 + lane];
            float kb = kh_s[h * 65 + lane + 32];
            float qa = q0p[h];
            float qb = q1p[h];
            float wvv = wv_s[h];
            s00 += wvv * tanha(qa + ka);
            s01 += wvv * tanha(qa + kb);
            s10 += wvv * tanha(qb + ka);
            s11 += wvv * tanha(qb + kb);
        }

        float* so = g_s + (size_t)(b * Qn + q0 + 2 * w) * Kn + k0;
        so[lane]           = s00;
        so[lane + 32]      = s01;
        so[Kn + lane]      = s10;
        so[Kn + lane + 32] = s11;
        __threadfence();
    }

    __syncthreads();
    if (tid == 0) last_s = (atomicAdd(&g_cnt_s[grp], 1) == 15) ? 1 : 0;
    __syncthreads();
    if (!last_s) return;
    if (tid == 0) g_cnt_s[grp] = 0;          // replay-safe reset

    const int lim = (vl + 15) & ~15;         // pv read bound
#pragma unroll
    for (int rr = 0; rr < 2; rr++) {
        const int row = b * Qn + q0 + 2 * w + rr;
        const float* srow = g_s + (size_t)row * Kn;
        float e_[32];
        float m = -3.4e38f;
#pragma unroll
        for (int t = 0; t < 32; t++) {
            int k = t * 32 + lane;
            e_[t] = (k < vl) ? srow[k] : -1e6f;
            m = fmaxf(m, e_[t]);
        }
#pragma unroll
        for (int o = 16; o > 0; o >>= 1) m = fmaxf(m, __shfl_xor_sync(0xffffffffu, m, o));
        float Z = 0.f;
#pragma unroll
        for (int t = 0; t < 32; t++) {
            e_[t] = ex2a((e_[t] - m) * 1.4426950408889634f);
            Z += e_[t];
        }
#pragma unroll
        for (int o = 16; o > 0; o >>= 1) Z += __shfl_xor_sync(0xffffffffu, Z, o);
        const float invZ = 1.0f / Z;

        float* prow = g_p + (size_t)row * Kn;
#pragma unroll
        for (int t = 0; t < 32; t++) {
            if (t * 32 < lim) prow[t * 32 + lane] = e_[t] * invZ;
        }
    }
}

// ---------------------------------------------------------------------------
// Partial P@V with packed f32x2 FMA (FFMA2). Grid = 512 CTAs, 256 threads.
// p duplicated in smem as (p,p) u64 -> broadcast LDS.64, zero in-loop packing.
// V read as ulonglong2 (LDS.128 reinterpret). rn rounding per element ->
// results bit-identical to scalar. Fused deterministic last-CTA reduction.
// ---------------------------------------------------------------------------
__global__ void pv_kernel(const float* __restrict__ v, const int* __restrict__ vlens,
                          float* __restrict__ out) {
    __shared__ __align__(16) float v_s[16 * 256];   // 16 KB
    __shared__ __align__(16) float2 p2_s[16 * 16];  // 2 KB, duplicated pairs
    __shared__ int last_s;

    const int bx  = blockIdx.x;
    const int ks  =  bx       & 3;
    const int dvs = (bx >> 2) & 1;
    const int qt  = (bx >> 3) & 15;
    const int b   =  bx >> 7;
    const int q0  = qt * 16;
    const int dv0 = dvs * 256;
    const int grp = bx >> 2;                        // 0..127

    const int tid  = threadIdx.x;
    const int lane = tid & 31;
    const int w    = tid >> 5;
    const int vl   = vlens[b];

    const int qg  = (w & 3) * 4;
    const int dvh = (w >> 2) * 32;
    const int n3  = (vl + 15) >> 4;

    const float* vb = v + (size_t)b * Kn * DV + dv0;
    const float* pg = g_p + (size_t)(b * Qn + q0) * Kn;

    float4 vpre[4];
    float  ppre;
    {
        const int k0 = ks * 16;
#pragma unroll
        for (int i = 0; i < 4; i++) {
            int e = tid + 256 * i;
            vpre[i] = *(const float4*)&vb[(size_t)(k0 + (e >> 6)) * DV + (e & 63) * 4];
        }
        ppre = pg[(size_t)(tid >> 4) * Kn + k0 + (tid & 15)];
    }

    unsigned long long acc2[4][2];
#pragma unroll
    for (int r = 0; r < 4; r++) { acc2[r][0] = 0ull; acc2[r][1] = 0ull; }

    for (int t = ks; t < n3; t += 4) {
        __syncthreads();
#pragma unroll
        for (int i = 0; i < 4; i++) {
            int e = tid + 256 * i;
            *(float4*)&v_s[(e >> 6) * 256 + (e & 63) * 4] = vpre[i];
        }
        p2_s[(tid >> 4) * 16 + (tid & 15)] = make_float2(ppre, ppre);
        __syncthreads();
        if (t + 4 < n3) {
            const int kn = (t + 4) * 16;
#pragma unroll
            for (int i = 0; i < 4; i++) {
                int e = tid + 256 * i;
                vpre[i] = *(const float4*)&vb[(size_t)(kn + (e >> 6)) * DV + (e & 63) * 4];
            }
            ppre = pg[(size_t)(tid >> 4) * Kn + kn + (tid & 15)];
        }
        const unsigned long long* pp = (const unsigned long long*)p2_s;
#pragma unroll
        for (int kk = 0; kk < 16; kk++) {
            ulonglong2 vv = *(const ulonglong2*)&v_s[kk * 256 + (dvh + lane) * 4];
            unsigned long long pq0 = pp[(qg + 0) * 16 + kk];
            unsigned long long pq1 = pp[(qg + 1) * 16 + kk];
            unsigned long long pq2 = pp[(qg + 2) * 16 + kk];
            unsigned long long pq3 = pp[(qg + 3) * 16 + kk];
            fma2(acc2[0][0], pq0, vv.x); fma2(acc2[0][1], pq0, vv.y);
            fma2(acc2[1][0], pq1, vv.x); fma2(acc2[1][1], pq1, vv.y);
            fma2(acc2[2][0], pq2, vv.x); fma2(acc2[2][1], pq2, vv.y);
            fma2(acc2[3][0], pq3, vv.x); fma2(acc2[3][1], pq3, vv.y);
        }
    }

    {
        float* po = g_po[ks];
#pragma unroll
        for (int r = 0; r < 4; r++) {
            float2 lo = up2(acc2[r][0]);
            float2 hi = up2(acc2[r][1]);
            float4 o = make_float4(lo.x, lo.y, hi.x, hi.y);
            *(float4*)&po[(size_t)(b * Qn + q0 + qg + r) * DV + dv0 + (dvh + lane) * 4] = o;
        }
    }

    __threadfence();
    __syncthreads();
    if (tid == 0) last_s = (atomicAdd(&g_cnt_v[grp], 1) == 3) ? 1 : 0;
    __syncthreads();
    if (last_s) {
        if (tid == 0) g_cnt_v[grp] = 0;   // replay-safe reset
#pragma unroll
        for (int j = 0; j < 4; j++) {
            int idx = j * 256 + tid;
            int r   = idx >> 6;
            int c   = idx & 63;
            size_t g = (size_t)(b * Qn + q0 + r) * (DV / 4) + (dv0 / 4) + c;
            const float4 a = ((const float4*)g_po[0])[g];
            const float4 bb = ((const float4*)g_po[1])[g];
            const float4 cc = ((const float4*)g_po[2])[g];
            const float4 dd = ((const float4*)g_po[3])[g];
            ((float4*)out)[g] = make_float4((a.x + bb.x) + (cc.x + dd.x),
                                            (a.y + bb.y) + (cc.y + dd.y),
                                            (a.z + bb.z) + (cc.z + dd.z),
                                            (a.w + bb.w) + (cc.w + dd.w));
        }
    }
}

// ---------------------------------------------------------------------------
extern "C" void kernel_launch(void* const* d_in, const int* in_sizes, int n_in,
                              void* d_out, int out_size) {
    const float* q    = (const float*)d_in[0];
    const float* k    = (const float*)d_in[1];
    const float* v    = (const float*)d_in[2];
    const int*   vlen = (const int*)d_in[3];
    const float* w_q  = (const float*)d_in[4];
    const float* w_k  = (const float*)d_in[5];
    const float* w_v  = (const float*)d_in[6];
    float*       out  = (float*)d_out;

    proj_kernel<<<640, 128>>>(q, w_q, k, w_k);
    score_kernel<<<1024, 256>>>(vlen, w_v);
    pv_kernel<<<512, 256>>>(v, vlen, out);
}

// round 16
// speedup vs baseline: 1.0611x; 1.0611x over previous
#include <cuda_runtime.h>

#define B  4
#define Qn 256
#define Kn 1024
#define Dd 512
#define Hh 128
#define DV 512

#define ROWS_ALL (B * Qn + B * Kn)          // 5120 projected rows total

__device__ float g_qh[B * Qn * Hh];         // 512 KB
__device__ float g_kh[B * Kn * Hh];         // 2 MB
__device__ float g_s[B * Qn * Kn];          // 4 MB raw scores
__device__ float g_p[B * Qn * Kn];          // 4 MB normalized probs
__device__ float g_pp[4][ROWS_ALL * Hh];    // 10 MB proj K-split partials
__device__ float g_po[4][B * Qn * DV];      // 8 MB pv K-split partials
__device__ int   g_cnt_p[320];              // proj group counters (zero-init)
__device__ int   g_cnt_s[B * 16];           // score group counters (zero-init)
__device__ int   g_cnt_v[B * 16 * 2];       // pv group counters (zero-init)

__device__ __forceinline__ float ex2a(float x) {
    float r; asm("ex2.approx.f32 %0, %1;" : "=f"(r) : "f"(x)); return r;
}
__device__ __forceinline__ float tanha(float x) {
    float r; asm("tanh.approx.f32 %0, %1;" : "=f"(r) : "f"(x)); return r;
}

// ---------------------------------------------------------------------------
// Projection GEMM, K-split 4 + fused deterministic last-CTA reduction.
// Grid 1280 x 128: bid = ((rt*2 + ht) << 2) | ks; rt row-tile (32 rows),
// ht H-half (64), ks D-quarter (128). ~8.6 CTAs/SM for latency hiding.
// Last CTA of each 4-group re-reads ALL partials in fixed order -> the
// reduction order is schedule-independent (deterministic).
// ---------------------------------------------------------------------------
__global__ void proj_kernel(const float* __restrict__ Xq, const float* __restrict__ Wq,
                            const float* __restrict__ Xk, const float* __restrict__ Wk) {
    __shared__ float Xs[32 * 36];
    __shared__ float Ws[32 * 68];
    __shared__ int last_s;

    const int bid = blockIdx.x;
    const int ks  = bid & 3;
    const int ht  = (bid >> 2) & 1;
    const int rt  = bid >> 3;
    const int r0  = rt * 32;
    const int h0  = ht * 64;
    const int d0  = ks * 128;
    const int grp = bid >> 2;                // 0..319

    const float* Xbase = (r0 < B * Qn) ? (Xq + (size_t)r0 * Dd)
                                       : (Xk + (size_t)(r0 - B * Qn) * Dd);
    const float* W = (r0 < B * Qn) ? Wq : Wk;

    const int tid = threadIdx.x;
    const int tx  = tid & 15;
    const int ty  = tid >> 4;

    float acc[4][4];
#pragma unroll
    for (int r = 0; r < 4; r++)
#pragma unroll
        for (int c = 0; c < 4; c++) acc[r][c] = 0.0f;

    for (int s = 0; s < 4; s++) {
        const int ds = d0 + s * 32;
        __syncthreads();
#pragma unroll
        for (int i = 0; i < 2; i++) {
            int e = tid + 128 * i;
            int r = e >> 3, c4 = (e & 7) * 4;
            float4 xv = *(const float4*)&Xbase[(size_t)r * Dd + ds + c4];
            Xs[(c4 + 0) * 36 + r] = xv.x;
            Xs[(c4 + 1) * 36 + r] = xv.y;
            Xs[(c4 + 2) * 36 + r] = xv.z;
            Xs[(c4 + 3) * 36 + r] = xv.w;
        }
#pragma unroll
        for (int i = 0; i < 4; i++) {
            int e = tid + 128 * i;
            int h = e >> 3, c4 = (e & 7) * 4;
            float4 wv = *(const float4*)&W[(size_t)(h0 + h) * Dd + ds + c4];
            Ws[(c4 + 0) * 68 + h] = wv.x;
            Ws[(c4 + 1) * 68 + h] = wv.y;
            Ws[(c4 + 2) * 68 + h] = wv.z;
            Ws[(c4 + 3) * 68 + h] = wv.w;
        }
        __syncthreads();
#pragma unroll
        for (int dd = 0; dd < 32; dd++) {
            float4 xv = *(const float4*)&Xs[dd * 36 + ty * 4];
            float4 wv = *(const float4*)&Ws[dd * 68 + tx * 4];
            acc[0][0] += xv.x * wv.x; acc[0][1] += xv.x * wv.y;
            acc[0][2] += xv.x * wv.z; acc[0][3] += xv.x * wv.w;
            acc[1][0] += xv.y * wv.x; acc[1][1] += xv.y * wv.y;
            acc[1][2] += xv.y * wv.z; acc[1][3] += xv.y * wv.w;
            acc[2][0] += xv.z * wv.x; acc[2][1] += xv.z * wv.y;
            acc[2][2] += xv.z * wv.z; acc[2][3] += xv.z * wv.w;
            acc[3][0] += xv.w * wv.x; acc[3][1] += xv.w * wv.y;
            acc[3][2] += xv.w * wv.z; acc[3][3] += xv.w * wv.w;
        }
    }

    float* pp = g_pp[ks];
#pragma unroll
    for (int r = 0; r < 4; r++) {
        float4 o = make_float4(acc[r][0], acc[r][1], acc[r][2], acc[r][3]);
        *(float4*)&pp[(size_t)(r0 + ty * 4 + r) * Hh + h0 + tx * 4] = o;
    }

    __threadfence();
    __syncthreads();
    if (tid == 0) last_s = (atomicAdd(&g_cnt_p[grp], 1) == 3) ? 1 : 0;
    __syncthreads();
    if (last_s) {
        if (tid == 0) g_cnt_p[grp] = 0;      // replay-safe reset
        float* Out = (r0 < B * Qn) ? (g_qh + (size_t)r0 * Hh)
                                   : (g_kh + (size_t)(r0 - B * Qn) * Hh);
#pragma unroll
        for (int r = 0; r < 4; r++) {
            const int rr = ty * 4 + r;
            const size_t off = (size_t)(r0 + rr) * Hh + h0 + tx * 4;
            float4 p0 = *(const float4*)&g_pp[0][off];
            float4 p1 = *(const float4*)&g_pp[1][off];
            float4 p2 = *(const float4*)&g_pp[2][off];
            float4 p3 = *(const float4*)&g_pp[3][off];
            float4 o = make_float4((p0.x + p1.x) + (p2.x + p3.x),
                                   (p0.y + p1.y) + (p2.y + p3.y),
                                   (p0.z + p1.z) + (p2.z + p3.z),
                                   (p0.w + p1.w) + (p2.w + p3.w));
            *(float4*)&Out[(size_t)rr * Hh + h0 + tx * 4] = o;
        }
    }
}

// ---------------------------------------------------------------------------
// Scores kernel with fused last-CTA softmax (R14). Grid = 1024 x 256.
// ---------------------------------------------------------------------------
__global__ void score_kernel(const int* __restrict__ vlens,
                             const float* __restrict__ w_v) {
    __shared__ float kh_s[Hh * 65];
    __shared__ float qh_s[16 * Hh];
    __shared__ float wv_s[Hh];
    __shared__ int last_s;

    const int bx = blockIdx.x;
    const int b  = bx >> 8;
    const int qt = (bx >> 4) & 15;
    const int kt = bx & 15;
    const int q0 = qt * 16;
    const int k0 = kt * 64;
    const int grp = bx >> 4;                 // 0..63

    const int tid  = threadIdx.x;
    const int lane = tid & 31;
    const int w    = tid >> 5;
    const int vl   = vlens[b];

    if (k0 < vl) {
        {
            const float4* src = (const float4*)(g_qh + (size_t)(b * Qn + q0) * Hh);
            ((float4*)qh_s)[tid]       = src[tid];
            ((float4*)qh_s)[tid + 256] = src[tid + 256];
        }
        if (tid < Hh) wv_s[tid] = w_v[tid];

        {
            const float* khg = g_kh + (size_t)(b * Kn + k0) * Hh;
#pragma unroll
            for (int i = 0; i < 8; i++) {
                int e  = tid + 256 * i;
                int kr = e >> 5;
                int h4 = (e & 31) * 4;
                float4 vv = *(const float4*)&khg[(size_t)kr * Hh + h4];
                kh_s[(h4 + 0) * 65 + kr] = vv.x;
                kh_s[(h4 + 1) * 65 + kr] = vv.y;
                kh_s[(h4 + 2) * 65 + kr] = vv.z;
                kh_s[(h4 + 3) * 65 + kr] = vv.w;
            }
        }
        __syncthreads();

        const float* q0p = qh_s + (2 * w) * Hh;
        const float* q1p = qh_s + (2 * w + 1) * Hh;

        float s00 = 0.f, s01 = 0.f, s10 = 0.f, s11 = 0.f;
#pragma unroll 4
        for (int h = 0; h < Hh; h++) {
            float ka = kh_s[h * 65 + lane];
            float kb = kh_s[h * 65 + lane + 32];
            float qa = q0p[h];
            float qb = q1p[h];
            float wvv = wv_s[h];
            s00 += wvv * tanha(qa + ka);
            s01 += wvv * tanha(qa + kb);
            s10 += wvv * tanha(qb + ka);
            s11 += wvv * tanha(qb + kb);
        }

        float* so = g_s + (size_t)(b * Qn + q0 + 2 * w) * Kn + k0;
        so[lane]           = s00;
        so[lane + 32]      = s01;
        so[Kn + lane]      = s10;
        so[Kn + lane + 32] = s11;
        __threadfence();
    }

    __syncthreads();
    if (tid == 0) last_s = (atomicAdd(&g_cnt_s[grp], 1) == 15) ? 1 : 0;
    __syncthreads();
    if (!last_s) return;
    if (tid == 0) g_cnt_s[grp] = 0;          // replay-safe reset

    const int lim = (vl + 15) & ~15;         // pv read bound
#pragma unroll
    for (int rr = 0; rr < 2; rr++) {
        const int row = b * Qn + q0 + 2 * w + rr;
        const float* srow = g_s + (size_t)row * Kn;
        float e_[32];
        float m = -3.4e38f;
#pragma unroll
        for (int t = 0; t < 32; t++) {
            int k = t * 32 + lane;
            e_[t] = (k < vl) ? srow[k] : -1e6f;
            m = fmaxf(m, e_[t]);
        }
#pragma unroll
        for (int o = 16; o > 0; o >>= 1) m = fmaxf(m, __shfl_xor_sync(0xffffffffu, m, o));
        float Z = 0.f;
#pragma unroll
        for (int t = 0; t < 32; t++) {
            e_[t] = ex2a((e_[t] - m) * 1.4426950408889634f);
            Z += e_[t];
        }
#pragma unroll
        for (int o = 16; o > 0; o >>= 1) Z += __shfl_xor_sync(0xffffffffu, Z, o);
        const float invZ = 1.0f / Z;

        float* prow = g_p + (size_t)row * Kn;
#pragma unroll
        for (int t = 0; t < 32; t++) {
            if (t * 32 < lim) prow[t * 32 + lane] = e_[t] * invZ;
        }
    }
}

// ---------------------------------------------------------------------------
// Partial P@V (R14 scalar, validated): reg-staged float4 p, 4-way parity
// K-split, fused deterministic last-CTA reduction. Grid = 512 x 256.
// ---------------------------------------------------------------------------
__global__ void pv_kernel(const float* __restrict__ v, const int* __restrict__ vlens,
                          float* __restrict__ out) {
    __shared__ __align__(16) float v_s[16 * 256];   // 16 KB
    __shared__ __align__(16) float p_s[16 * 16];    // 1 KB
    __shared__ int last_s;

    const int bx  = blockIdx.x;
    const int ks  =  bx       & 3;
    const int dvs = (bx >> 2) & 1;
    const int qt  = (bx >> 3) & 15;
    const int b   =  bx >> 7;
    const int q0  = qt * 16;
    const int dv0 = dvs * 256;
    const int grp = bx >> 2;                        // 0..127

    const int tid  = threadIdx.x;
    const int lane = tid & 31;
    const int w    = tid >> 5;
    const int vl   = vlens[b];

    const int qg  = (w & 3) * 4;
    const int dvh = (w >> 2) * 32;
    const int n3  = (vl + 15) >> 4;

    const float* vb = v + (size_t)b * Kn * DV + dv0;
    const float* pg = g_p + (size_t)(b * Qn + q0) * Kn;

    float4 vpre[4];
    float  ppre;
    {
        const int k0 = ks * 16;
#pragma unroll
        for (int i = 0; i < 4; i++) {
            int e = tid + 256 * i;
            vpre[i] = *(const float4*)&vb[(size_t)(k0 + (e >> 6)) * DV + (e & 63) * 4];
        }
        ppre = pg[(size_t)(tid >> 4) * Kn + k0 + (tid & 15)];
    }

    float4 acc[4];
#pragma unroll
    for (int r = 0; r < 4; r++) acc[r] = make_float4(0.f, 0.f, 0.f, 0.f);

    for (int t = ks; t < n3; t += 4) {
        __syncthreads();
#pragma unroll
        for (int i = 0; i < 4; i++) {
            int e = tid + 256 * i;
            *(float4*)&v_s[(e >> 6) * 256 + (e & 63) * 4] = vpre[i];
        }
        p_s[(tid >> 4) * 16 + (tid & 15)] = ppre;
        __syncthreads();
        if (t + 4 < n3) {
            const int kn = (t + 4) * 16;
#pragma unroll
            for (int i = 0; i < 4; i++) {
                int e = tid + 256 * i;
                vpre[i] = *(const float4*)&vb[(size_t)(kn + (e >> 6)) * DV + (e & 63) * 4];
            }
            ppre = pg[(size_t)(tid >> 4) * Kn + kn + (tid & 15)];
        }
#pragma unroll
        for (int k4 = 0; k4 < 4; k4++) {
            float4 pq0 = *(const float4*)&p_s[(qg + 0) * 16 + k4 * 4];
            float4 pq1 = *(const float4*)&p_s[(qg + 1) * 16 + k4 * 4];
            float4 pq2 = *(const float4*)&p_s[(qg + 2) * 16 + k4 * 4];
            float4 pq3 = *(const float4*)&p_s[(qg + 3) * 16 + k4 * 4];
            const float a0[4] = {pq0.x, pq0.y, pq0.z, pq0.w};
            const float a1[4] = {pq1.x, pq1.y, pq1.z, pq1.w};
            const float a2[4] = {pq2.x, pq2.y, pq2.z, pq2.w};
            const float a3[4] = {pq3.x, pq3.y, pq3.z, pq3.w};
#pragma unroll
            for (int kk = 0; kk < 4; kk++) {
                float4 vv = *(const float4*)&v_s[(k4 * 4 + kk) * 256 + (dvh + lane) * 4];
                acc[0].x += a0[kk] * vv.x; acc[0].y += a0[kk] * vv.y;
                acc[0].z += a0[kk] * vv.z; acc[0].w += a0[kk] * vv.w;
                acc[1].x += a1[kk] * vv.x; acc[1].y += a1[kk] * vv.y;
                acc[1].z += a1[kk] * vv.z; acc[1].w += a1[kk] * vv.w;
                acc[2].x += a2[kk] * vv.x; acc[2].y += a2[kk] * vv.y;
                acc[2].z += a2[kk] * vv.z; acc[2].w += a2[kk] * vv.w;
                acc[3].x += a3[kk] * vv.x; acc[3].y += a3[kk] * vv.y;
                acc[3].z += a3[kk] * vv.z; acc[3].w += a3[kk] * vv.w;
            }
        }
    }

    {
        float* po = g_po[ks];
#pragma unroll
        for (int r = 0; r < 4; r++)
            *(float4*)&po[(size_t)(b * Qn + q0 + qg + r) * DV + dv0 + (dvh + lane) * 4] = acc[r];
    }

    __threadfence();
    __syncthreads();
    if (tid == 0) last_s = (atomicAdd(&g_cnt_v[grp], 1) == 3) ? 1 : 0;
    __syncthreads();
    if (last_s) {
        if (tid == 0) g_cnt_v[grp] = 0;   // replay-safe reset
#pragma unroll
        for (int j = 0; j < 4; j++) {
            int idx = j * 256 + tid;
            int r   = idx >> 6;
            int c   = idx & 63;
            size_t g = (size_t)(b * Qn + q0 + r) * (DV / 4) + (dv0 / 4) + c;
            const float4 a = ((const float4*)g_po[0])[g];
            const float4 bb = ((const float4*)g_po[1])[g];
            const float4 cc = ((const float4*)g_po[2])[g];
            const float4 dd = ((const float4*)g_po[3])[g];
            ((float4*)out)[g] = make_float4((a.x + bb.x) + (cc.x + dd.x),
                                            (a.y + bb.y) + (cc.y + dd.y),
                                            (a.z + bb.z) + (cc.z + dd.z),
                                            (a.w + bb.w) + (cc.w + dd.w));
        }
    }
}

// ---------------------------------------------------------------------------
extern "C" void kernel_launch(void* const* d_in, const int* in_sizes, int n_in,
                              void* d_out, int out_size) {
    const float* q    = (const float*)d_in[0];
    const float* k    = (const float*)d_in[1];
    const float* v    = (const float*)d_in[2];
    const int*   vlen = (const int*)d_in[3];
    const float* w_q  = (const float*)d_in[4];
    const float* w_k  = (const float*)d_in[5];
    const float* w_v  = (const float*)d_in[6];
    float*       out  = (float*)d_out;

    proj_kernel<<<1280, 128>>>(q, w_q, k, w_k);
    score_kernel<<<1024, 256>>>(vlen, w_v);
    pv_kernel<<<512, 256>>>(v, vlen, out);
}